// round 1
// baseline (speedup 1.0000x reference)
#include <cuda_runtime.h>
#include <math.h>

// Problem dims (fixed by the dataset)
#define T_TOK 2048   // B*S
#define H_DIM 2048
#define I_DIM 4096
#define E_NUM 8

// ---------------- scratch (device globals; no runtime allocation) ----------
__device__ float g_scale[E_NUM];                     // router_scores[0, 0:E]
__device__ float g_act_exp[E_NUM * I_DIM];           // silu(gate)*up per expert
__device__ float g_expert_sum[H_DIM];                // sum_e expert_out[e]
__device__ float g_gate_s[(size_t)T_TOK * I_DIM];    // shared gate (then act)
__device__ float g_up_s[(size_t)T_TOK * I_DIM];      // shared up

// ---------------- router: logits, top-1 mask, sigmoid ----------------------
__global__ void router_kernel(const float* __restrict__ hs,
                              const float* __restrict__ rw,
                              float* __restrict__ scores /* [E, T] */) {
    int t = blockIdx.x;
    int tid = threadIdx.x;                // 256 threads
    const float* x = hs + (size_t)t * H_DIM;

    float acc[E_NUM];
#pragma unroll
    for (int e = 0; e < E_NUM; e++) acc[e] = 0.f;

    for (int h = tid; h < H_DIM; h += 256) {
        float xv = x[h];
#pragma unroll
        for (int e = 0; e < E_NUM; e++) acc[e] += xv * rw[e * H_DIM + h];
    }
    // warp reduce
#pragma unroll
    for (int off = 16; off; off >>= 1) {
#pragma unroll
        for (int e = 0; e < E_NUM; e++)
            acc[e] += __shfl_down_sync(0xffffffffu, acc[e], off);
    }
    __shared__ float red[8][E_NUM];
    int warp = tid >> 5, lane = tid & 31;
    if (lane == 0) {
#pragma unroll
        for (int e = 0; e < E_NUM; e++) red[warp][e] = acc[e];
    }
    __syncthreads();
    if (tid == 0) {
        float logit[E_NUM];
#pragma unroll
        for (int e = 0; e < E_NUM; e++) {
            float s = 0.f;
#pragma unroll
            for (int w = 0; w < 8; w++) s += red[w][e];
            logit[e] = s;
        }
        int amax = 0; float best = logit[0];
#pragma unroll
        for (int e = 1; e < E_NUM; e++)
            if (logit[e] > best) { best = logit[e]; amax = e; }
        float sig = 1.f / (1.f + expf(-best));
#pragma unroll
        for (int e = 0; e < E_NUM; e++)
            scores[(size_t)e * T_TOK + t] = (e == amax) ? sig : 0.f;
        if (t < E_NUM) g_scale[t] = (amax == 0) ? sig : 0.f;
    }
}

// ---------------- expert gate/up GEMV (skips zero-score experts) -----------
// grid: (I/8, E), block: 256. One warp per output row i, computes both
// gate and up dots, writes silu(s*g)*(s*u).
__global__ void expert_gateup_kernel(const float* __restrict__ hs,
                                     const float* __restrict__ gw,
                                     const float* __restrict__ uw) {
    int e = blockIdx.y;
    float s = g_scale[e];
    if (s == 0.f) return;                 // skip inactive expert: no HBM read
    int warp = threadIdx.x >> 5, lane = threadIdx.x & 31;
    int i = blockIdx.x * 8 + warp;

    const float4* x4 = (const float4*)(hs + (size_t)e * H_DIM);
    const float4* g4 = (const float4*)(gw + ((size_t)e * I_DIM + i) * H_DIM);
    const float4* u4 = (const float4*)(uw + ((size_t)e * I_DIM + i) * H_DIM);

    float ga = 0.f, ua = 0.f;
    for (int k = lane; k < H_DIM / 4; k += 32) {
        float4 xv = x4[k], gv = g4[k], uv = u4[k];
        ga += xv.x * gv.x + xv.y * gv.y + xv.z * gv.z + xv.w * gv.w;
        ua += xv.x * uv.x + xv.y * uv.y + xv.z * uv.z + xv.w * uv.w;
    }
#pragma unroll
    for (int off = 16; off; off >>= 1) {
        ga += __shfl_down_sync(0xffffffffu, ga, off);
        ua += __shfl_down_sync(0xffffffffu, ua, off);
    }
    if (lane == 0) {
        ga *= s; ua *= s;
        float act = ga / (1.f + expf(-ga)) * ua;
        g_act_exp[e * I_DIM + i] = act;
    }
}

// ---------------- expert down GEMV + sum over experts ----------------------
// grid: H blocks of 256 threads. Always writes (0 when no expert active).
__global__ void expert_down_kernel(const float* __restrict__ dw) {
    int h = blockIdx.x;
    int tid = threadIdx.x;
    float acc = 0.f;
    for (int e = 0; e < E_NUM; e++) {
        if (g_scale[e] == 0.f) continue;
        const float4* w4 = (const float4*)(dw + ((size_t)e * H_DIM + h) * I_DIM);
        const float4* a4 = (const float4*)(g_act_exp + e * I_DIM);
        for (int k = tid; k < I_DIM / 4; k += 256) {
            float4 wv = w4[k], av = a4[k];
            acc += wv.x * av.x + wv.y * av.y + wv.z * av.z + wv.w * av.w;
        }
    }
    __shared__ float red[256];
    red[tid] = acc;
    __syncthreads();
    for (int s = 128; s; s >>= 1) {
        if (tid < s) red[tid] += red[tid + s];
        __syncthreads();
    }
    if (tid == 0) g_expert_sum[h] = red[0];
}

// ---------------- fp32 SGEMM, C[M,N] = A[M,K] @ B[N,K]^T (+ bias[N]) -------
// 128x128x8 tile, 256 threads, 8x8 per thread in 2x2 float4 quads,
// double-buffered shared memory. M,N mult of 128; K mult of 8.
__global__ __launch_bounds__(256)
void sgemm_nt(const float* __restrict__ A, const float* __restrict__ B,
              float* __restrict__ C, int M, int N, int K,
              const float* __restrict__ bias) {
    const int BM = 128, BN = 128, BK = 8;
    __shared__ float As[2][BK][BM];
    __shared__ float Bs[2][BK][BN];

    int tid = threadIdx.x;
    int bm = blockIdx.y * BM, bn = blockIdx.x * BN;

    // global-load mapping: each thread loads one float4 of A and one of B
    int grow = tid >> 1;            // 0..127
    int gcol = (tid & 1) * 4;       // 0 or 4
    const float* Aptr = A + (size_t)(bm + grow) * K + gcol;
    const float* Bptr = B + (size_t)(bn + grow) * K + gcol;

    // compute mapping: 16x16 threads, each owns 4+4 rows/cols split by 64
    int tx = tid & 15, ty = tid >> 4;

    float accum[8][8];
#pragma unroll
    for (int i = 0; i < 8; i++)
#pragma unroll
        for (int j = 0; j < 8; j++) accum[i][j] = 0.f;

    // prologue: stage 0
    {
        float4 av = *(const float4*)Aptr;
        float4 bv = *(const float4*)Bptr;
        As[0][gcol + 0][grow] = av.x; As[0][gcol + 1][grow] = av.y;
        As[0][gcol + 2][grow] = av.z; As[0][gcol + 3][grow] = av.w;
        Bs[0][gcol + 0][grow] = bv.x; Bs[0][gcol + 1][grow] = bv.y;
        Bs[0][gcol + 2][grow] = bv.z; Bs[0][gcol + 3][grow] = bv.w;
    }
    __syncthreads();

    int stage = 0;
    for (int k0 = 0; k0 < K; k0 += BK) {
        float4 av, bv;
        bool more = (k0 + BK) < K;
        if (more) {
            av = *(const float4*)(Aptr + k0 + BK);
            bv = *(const float4*)(Bptr + k0 + BK);
        }
        float a_frag[8], b_frag[8];
#pragma unroll
        for (int kk = 0; kk < BK; kk++) {
            *(float4*)&a_frag[0] = *(const float4*)&As[stage][kk][ty * 4];
            *(float4*)&a_frag[4] = *(const float4*)&As[stage][kk][64 + ty * 4];
            *(float4*)&b_frag[0] = *(const float4*)&Bs[stage][kk][tx * 4];
            *(float4*)&b_frag[4] = *(const float4*)&Bs[stage][kk][64 + tx * 4];
#pragma unroll
            for (int i = 0; i < 8; i++)
#pragma unroll
                for (int j = 0; j < 8; j++)
                    accum[i][j] += a_frag[i] * b_frag[j];
        }
        if (more) {
            int ns = stage ^ 1;
            As[ns][gcol + 0][grow] = av.x; As[ns][gcol + 1][grow] = av.y;
            As[ns][gcol + 2][grow] = av.z; As[ns][gcol + 3][grow] = av.w;
            Bs[ns][gcol + 0][grow] = bv.x; Bs[ns][gcol + 1][grow] = bv.y;
            Bs[ns][gcol + 2][grow] = bv.z; Bs[ns][gcol + 3][grow] = bv.w;
            __syncthreads();
            stage = ns;
        }
    }

    // epilogue
    float bsum[8];
#pragma unroll
    for (int j = 0; j < 8; j++) {
        int col = bn + ((j < 4) ? (tx * 4 + j) : (64 + tx * 4 + j - 4));
        bsum[j] = bias ? bias[col] : 0.f;
    }
#pragma unroll
    for (int i = 0; i < 8; i++) {
        int row = bm + ((i < 4) ? (ty * 4 + i) : (64 + ty * 4 + i - 4));
        float* crow = C + (size_t)row * N + bn;
        float4 v0, v1;
        v0.x = accum[i][0] + bsum[0]; v0.y = accum[i][1] + bsum[1];
        v0.z = accum[i][2] + bsum[2]; v0.w = accum[i][3] + bsum[3];
        v1.x = accum[i][4] + bsum[4]; v1.y = accum[i][5] + bsum[5];
        v1.z = accum[i][6] + bsum[6]; v1.w = accum[i][7] + bsum[7];
        *(float4*)(crow + tx * 4)      = v0;
        *(float4*)(crow + 64 + tx * 4) = v1;
    }
}

// ---------------- elementwise silu(gate)*up (in place into gate) -----------
__global__ void silu_mul_kernel(float* __restrict__ g,
                                const float* __restrict__ u) {
    size_t i = ((size_t)blockIdx.x * 256 + threadIdx.x) * 4;
    float4 gv = *(float4*)(g + i);
    float4 uv = *(const float4*)(u + i);
    gv.x = gv.x / (1.f + expf(-gv.x)) * uv.x;
    gv.y = gv.y / (1.f + expf(-gv.y)) * uv.y;
    gv.z = gv.z / (1.f + expf(-gv.z)) * uv.z;
    gv.w = gv.w / (1.f + expf(-gv.w)) * uv.w;
    *(float4*)(g + i) = gv;
}

// ---------------- launch --------------------------------------------------
extern "C" void kernel_launch(void* const* d_in, const int* in_sizes, int n_in,
                              void* d_out, int out_size) {
    const float* hs  = (const float*)d_in[0];
    const float* rw  = (const float*)d_in[1];
    const float* sgw = (const float*)d_in[2];
    const float* suw = (const float*)d_in[3];
    const float* sdw = (const float*)d_in[4];
    const float* egw = (const float*)d_in[5];
    const float* euw = (const float*)d_in[6];
    const float* edw = (const float*)d_in[7];

    float* out    = (float*)d_out;
    float* scores = out + (size_t)T_TOK * H_DIM;

    float *p_gate, *p_up, *p_esum;
    cudaGetSymbolAddress((void**)&p_gate, g_gate_s);
    cudaGetSymbolAddress((void**)&p_up,   g_up_s);
    cudaGetSymbolAddress((void**)&p_esum, g_expert_sum);

    // 1. router (+ writes g_scale, router_scores output)
    router_kernel<<<T_TOK, 256>>>(hs, rw, scores);

    // 2. expert gate/up GEMV (data-dependent skip)
    expert_gateup_kernel<<<dim3(I_DIM / 8, E_NUM), 256>>>(hs, egw, euw);

    // 3. expert down GEMV + sum over experts
    expert_down_kernel<<<H_DIM, 256>>>(edw);

    // 4-5. shared gate & up GEMMs: [T,H] x [I,H]^T -> [T,I]
    dim3 g1(I_DIM / 128, T_TOK / 128);
    sgemm_nt<<<g1, 256>>>(hs, sgw, p_gate, T_TOK, I_DIM, H_DIM, nullptr);
    sgemm_nt<<<g1, 256>>>(hs, suw, p_up,   T_TOK, I_DIM, H_DIM, nullptr);

    // 6. act = silu(gate)*up (in place)
    silu_mul_kernel<<<(T_TOK * (I_DIM / 4)) / 256, 256>>>(p_gate, p_up);

    // 7. out = act @ down^T + expert_sum (broadcast over rows)
    dim3 g2(H_DIM / 128, T_TOK / 128);
    sgemm_nt<<<g2, 256>>>(p_gate, sdw, out, T_TOK, H_DIM, I_DIM, p_esum);
}

// round 3
// speedup vs baseline: 2.9914x; 2.9914x over previous
#include <cuda_runtime.h>
#include <math.h>
#include <stdint.h>

#define T_TOK 2048   // B*S
#define H_DIM 2048
#define I_DIM 4096
#define E_NUM 8

// ---------------- scratch (device globals; no runtime allocation) ----------
__device__ __align__(256) float g_scale[E_NUM];
__device__ __align__(256) float g_act_exp[E_NUM * I_DIM];
__device__ __align__(256) float g_expert_sum[H_DIM];
__device__ __align__(256) float g_act[(size_t)T_TOK * I_DIM];     // gate, then act
__device__ __align__(256) float g_hs_t[(size_t)T_TOK * H_DIM];    // tf32-rounded hs
__device__ __align__(256) float g_sgw_t[(size_t)I_DIM * H_DIM];
__device__ __align__(256) float g_suw_t[(size_t)I_DIM * H_DIM];
__device__ __align__(256) float g_sdw_t[(size_t)H_DIM * I_DIM];

// ============================ helpers ======================================
__device__ __forceinline__ uint32_t tf32_rna_bits(float x) {
    uint32_t r;
    asm("cvt.rna.tf32.f32 %0, %1;" : "=r"(r) : "f"(x));
    return r;
}

#define LDSM_X4(r0, r1, r2, r3, addr) \
    asm volatile("ldmatrix.sync.aligned.m8n8.x4.shared.b16 {%0,%1,%2,%3}, [%4];" \
                 : "=r"(r0), "=r"(r1), "=r"(r2), "=r"(r3) : "r"(addr))

#define MMA_TF32(d, a, b0, b1) \
    asm volatile("mma.sync.aligned.m16n8k8.row.col.f32.tf32.tf32.f32 " \
                 "{%0,%1,%2,%3}, {%4,%5,%6,%7}, {%8,%9}, {%0,%1,%2,%3};" \
                 : "+f"((d)[0]), "+f"((d)[1]), "+f"((d)[2]), "+f"((d)[3]) \
                 : "r"((a)[0]), "r"((a)[1]), "r"((a)[2]), "r"((a)[3]), \
                   "r"(b0), "r"(b1))

// ===================== tf32 rounding pass (RNA, unbiased) ==================
__global__ void tf32_round_kernel(const float4* __restrict__ in,
                                  uint4* __restrict__ out, int n4) {
    int i = blockIdx.x * 256 + threadIdx.x;
    if (i >= n4) return;
    float4 v = in[i];
    uint4 o;
    o.x = tf32_rna_bits(v.x); o.y = tf32_rna_bits(v.y);
    o.z = tf32_rna_bits(v.z); o.w = tf32_rna_bits(v.w);
    out[i] = o;
}

// ============ tf32 tensor-core GEMM: C[M,N] = A[M,K] @ B[N,K]^T ============
// 128x128x32 CTA tile, 8 warps (2x4), warp tile 64x32, mma.sync m16n8k8 tf32.
// Smem tiles padded to stride 36 floats (conflict-free ldmatrix).
// mode 0: C = acc + (bias ? bias[col] : 0)
// mode 1: C = tf32_rna( silu(aux[row,col]) * acc )   (aux may alias C)
#define LDS_F 36                       // floats per smem row (32 + 4 pad)
#define TILE_F (128 * LDS_F)           // 4608 floats per operand tile
#define STAGE_B (2 * TILE_F * 4)       // 36864 bytes per stage (A+B)
#define GEMM_SMEM (2 * STAGE_B)        // 73728

__device__ __forceinline__ void load_tile_ca(const float* __restrict__ A,
                                             const float* __restrict__ B,
                                             int K, int bm, int bn,
                                             uint32_t sbase, int kt, int st,
                                             int tid) {
    const float* Ag = A + (size_t)bm * K + kt * 32;
    const float* Bg = B + (size_t)bn * K + kt * 32;
    uint32_t s0 = sbase + st * STAGE_B;
#pragma unroll
    for (int j = 0; j < 8; j++) {
        int idx = tid + j * 256;          // 0..2047
        int isB = idx >> 10;
        int local = idx & 1023;
        int row = local >> 3, c4 = local & 7;
        const float* g = (isB ? Bg : Ag) + (size_t)row * K + c4 * 4;
        uint32_t sa = s0 + isB * (TILE_F * 4) + row * (LDS_F * 4) + c4 * 16;
        asm volatile("cp.async.cg.shared.global [%0], [%1], 16;" :: "r"(sa), "l"(g));
    }
    asm volatile("cp.async.commit_group;" ::: "memory");
}

__global__ __launch_bounds__(256, 2)
void gemm_tf32_mma(const float* __restrict__ A, const float* __restrict__ B,
                   float* __restrict__ C, int K, int N,
                   const float* __restrict__ bias,
                   const float* __restrict__ aux, int mode) {
    extern __shared__ char smem[];
    uint32_t sbase = (uint32_t)__cvta_generic_to_shared(smem);
    const int tid = threadIdx.x;
    const int wid = tid >> 5, lane = tid & 31;
    const int warp_m = wid & 1;          // 2 along M (64 rows each)
    const int warp_n = wid >> 1;         // 4 along N (32 cols each)
    const int bm = blockIdx.y * 128, bn = blockIdx.x * 128;

    // per-lane ldmatrix base offsets (bytes), stage 0
    // A frag x4: matrices (row+0/8) x (col+0/4): lane l -> row (l&7)+(l&8), col ((l>>4)&1)*4
    uint32_t a_off = ((warp_m * 64 + (lane & 7) + (lane & 8)) * LDS_F +
                      ((lane >> 4) & 1) * 4) * 4;
    // B frag x4 covers two 8-col n-tiles: lane l -> n (l&7)+((l>>4)&1)*8, col ((l>>3)&1)*4
    uint32_t b_off = (uint32_t)(TILE_F * 4) +
                     ((warp_n * 32 + (lane & 7) + ((lane >> 4) & 1) * 8) * LDS_F +
                      ((lane >> 3) & 1) * 4) * 4;

    float acc[4][4][4];
#pragma unroll
    for (int i = 0; i < 4; i++)
#pragma unroll
        for (int j = 0; j < 4; j++)
#pragma unroll
            for (int q = 0; q < 4; q++) acc[i][j][q] = 0.f;

    const int KT = K >> 5;
    load_tile_ca(A, B, K, bm, bn, sbase, 0, 0, tid);

    for (int kt = 0; kt < KT; kt++) {
        int st = kt & 1;
        if (kt + 1 < KT) {
            load_tile_ca(A, B, K, bm, bn, sbase, kt + 1, st ^ 1, tid);
            asm volatile("cp.async.wait_group 1;" ::: "memory");
        } else {
            asm volatile("cp.async.wait_group 0;" ::: "memory");
        }
        __syncthreads();

        uint32_t a_ptr = sbase + st * STAGE_B + a_off;
        uint32_t b_ptr = sbase + st * STAGE_B + b_off;
#pragma unroll
        for (int ks = 0; ks < 4; ks++) {
            uint32_t a[4][4];
#pragma unroll
            for (int mt = 0; mt < 4; mt++)
                LDSM_X4(a[mt][0], a[mt][1], a[mt][2], a[mt][3],
                        a_ptr + (mt * 16 * LDS_F + ks * 8) * 4);
            uint32_t b[2][4];   // [ntp][m0=nt0 k0, m1=nt0 k4, m2=nt1 k0, m3=nt1 k4]
#pragma unroll
            for (int ntp = 0; ntp < 2; ntp++)
                LDSM_X4(b[ntp][0], b[ntp][1], b[ntp][2], b[ntp][3],
                        b_ptr + (ntp * 16 * LDS_F + ks * 8) * 4);
#pragma unroll
            for (int mt = 0; mt < 4; mt++)
#pragma unroll
                for (int nt = 0; nt < 4; nt++)
                    MMA_TF32(acc[mt][nt], a[mt],
                             b[nt >> 1][(nt & 1) * 2], b[nt >> 1][(nt & 1) * 2 + 1]);
        }
        __syncthreads();
    }

    // epilogue
    int lrow = lane >> 2, lcol = lane & 3;
    int col0 = bn + warp_n * 32;
#pragma unroll
    for (int mt = 0; mt < 4; mt++) {
#pragma unroll
        for (int h = 0; h < 2; h++) {
            int row = bm + warp_m * 64 + mt * 16 + lrow + h * 8;
            float* crow = C + (size_t)row * N + col0;
            const float* arow = aux + (size_t)row * N + col0;   // mode 1 only
#pragma unroll
            for (int nt = 0; nt < 4; nt++) {
                int c = nt * 8 + lcol * 2;
                float v0 = acc[mt][nt][h * 2 + 0];
                float v1 = acc[mt][nt][h * 2 + 1];
                if (mode == 1) {
                    float2 gv = *reinterpret_cast<const float2*>(arow + c);
                    v0 = gv.x / (1.f + expf(-gv.x)) * v0;
                    v1 = gv.y / (1.f + expf(-gv.y)) * v1;
                    uint2 o = { tf32_rna_bits(v0), tf32_rna_bits(v1) };
                    *reinterpret_cast<uint2*>(crow + c) = o;
                } else {
                    if (bias) { v0 += bias[col0 + c]; v1 += bias[col0 + c + 1]; }
                    float2 o = { v0, v1 };
                    *reinterpret_cast<float2*>(crow + c) = o;
                }
            }
        }
    }
}

// ---------------- router: logits, top-1 mask, sigmoid ----------------------
__global__ void router_kernel(const float* __restrict__ hs,
                              const float* __restrict__ rw,
                              float* __restrict__ scores /* [E, T] */) {
    int t = blockIdx.x;
    int tid = threadIdx.x;
    const float* x = hs + (size_t)t * H_DIM;

    float acc[E_NUM];
#pragma unroll
    for (int e = 0; e < E_NUM; e++) acc[e] = 0.f;
    for (int h = tid; h < H_DIM; h += 256) {
        float xv = x[h];
#pragma unroll
        for (int e = 0; e < E_NUM; e++) acc[e] += xv * rw[e * H_DIM + h];
    }
#pragma unroll
    for (int off = 16; off; off >>= 1) {
#pragma unroll
        for (int e = 0; e < E_NUM; e++)
            acc[e] += __shfl_down_sync(0xffffffffu, acc[e], off);
    }
    __shared__ float red[8][E_NUM];
    int warp = tid >> 5, lane = tid & 31;
    if (lane == 0) {
#pragma unroll
        for (int e = 0; e < E_NUM; e++) red[warp][e] = acc[e];
    }
    __syncthreads();
    if (tid == 0) {
        float logit[E_NUM];
#pragma unroll
        for (int e = 0; e < E_NUM; e++) {
            float s = 0.f;
#pragma unroll
            for (int w = 0; w < 8; w++) s += red[w][e];
            logit[e] = s;
        }
        int amax = 0; float best = logit[0];
#pragma unroll
        for (int e = 1; e < E_NUM; e++)
            if (logit[e] > best) { best = logit[e]; amax = e; }
        float sig = 1.f / (1.f + expf(-best));
#pragma unroll
        for (int e = 0; e < E_NUM; e++)
            scores[(size_t)e * T_TOK + t] = (e == amax) ? sig : 0.f;
        if (t < E_NUM) g_scale[t] = (amax == 0) ? sig : 0.f;
    }
}

// ---------------- expert gate/up GEMV (skips zero-score experts) -----------
__global__ void expert_gateup_kernel(const float* __restrict__ hs,
                                     const float* __restrict__ gw,
                                     const float* __restrict__ uw) {
    int e = blockIdx.y;
    float s = g_scale[e];
    if (s == 0.f) return;
    int warp = threadIdx.x >> 5, lane = threadIdx.x & 31;
    int i = blockIdx.x * 8 + warp;

    const float4* x4 = (const float4*)(hs + (size_t)e * H_DIM);
    const float4* g4 = (const float4*)(gw + ((size_t)e * I_DIM + i) * H_DIM);
    const float4* u4 = (const float4*)(uw + ((size_t)e * I_DIM + i) * H_DIM);

    float ga = 0.f, ua = 0.f;
    for (int k = lane; k < H_DIM / 4; k += 32) {
        float4 xv = x4[k], gv = g4[k], uv = u4[k];
        ga += xv.x * gv.x + xv.y * gv.y + xv.z * gv.z + xv.w * gv.w;
        ua += xv.x * uv.x + xv.y * uv.y + xv.z * uv.z + xv.w * uv.w;
    }
#pragma unroll
    for (int off = 16; off; off >>= 1) {
        ga += __shfl_down_sync(0xffffffffu, ga, off);
        ua += __shfl_down_sync(0xffffffffu, ua, off);
    }
    if (lane == 0) {
        ga *= s; ua *= s;
        float act = ga / (1.f + expf(-ga)) * ua;
        g_act_exp[e * I_DIM + i] = act;
    }
}

// ---------------- expert down GEMV + sum over experts ----------------------
__global__ void expert_down_kernel(const float* __restrict__ dw) {
    int h = blockIdx.x;
    int tid = threadIdx.x;
    float acc = 0.f;
    for (int e = 0; e < E_NUM; e++) {
        if (g_scale[e] == 0.f) continue;
        const float4* w4 = (const float4*)(dw + ((size_t)e * H_DIM + h) * I_DIM);
        const float4* a4 = (const float4*)(g_act_exp + e * I_DIM);
        for (int k = tid; k < I_DIM / 4; k += 256) {
            float4 wv = w4[k], av = a4[k];
            acc += wv.x * av.x + wv.y * av.y + wv.z * av.z + wv.w * av.w;
        }
    }
    __shared__ float red[256];
    red[tid] = acc;
    __syncthreads();
    for (int s = 128; s; s >>= 1) {
        if (tid < s) red[tid] += red[tid + s];
        __syncthreads();
    }
    if (tid == 0) g_expert_sum[h] = red[0];
}

// ---------------- launch --------------------------------------------------
extern "C" void kernel_launch(void* const* d_in, const int* in_sizes, int n_in,
                              void* d_out, int out_size) {
    const float* hs  = (const float*)d_in[0];
    const float* rw  = (const float*)d_in[1];
    const float* sgw = (const float*)d_in[2];
    const float* suw = (const float*)d_in[3];
    const float* sdw = (const float*)d_in[4];
    const float* egw = (const float*)d_in[5];
    const float* euw = (const float*)d_in[6];
    const float* edw = (const float*)d_in[7];

    float* out    = (float*)d_out;
    float* scores = out + (size_t)T_TOK * H_DIM;

    float *p_act, *p_hs, *p_sgw, *p_suw, *p_sdw, *p_esum;
    cudaGetSymbolAddress((void**)&p_act,  g_act);
    cudaGetSymbolAddress((void**)&p_hs,   g_hs_t);
    cudaGetSymbolAddress((void**)&p_sgw,  g_sgw_t);
    cudaGetSymbolAddress((void**)&p_suw,  g_suw_t);
    cudaGetSymbolAddress((void**)&p_sdw,  g_sdw_t);
    cudaGetSymbolAddress((void**)&p_esum, g_expert_sum);

    cudaFuncSetAttribute(gemm_tf32_mma,
                         cudaFuncAttributeMaxDynamicSharedMemorySize, GEMM_SMEM);

    // 0. unbiased tf32 rounding of all tensor-core operands
    int n4 = T_TOK * H_DIM / 4;
    tf32_round_kernel<<<n4 / 256, 256>>>((const float4*)hs,  (uint4*)p_hs,  n4);
    n4 = I_DIM * H_DIM / 4;
    tf32_round_kernel<<<n4 / 256, 256>>>((const float4*)sgw, (uint4*)p_sgw, n4);
    tf32_round_kernel<<<n4 / 256, 256>>>((const float4*)suw, (uint4*)p_suw, n4);
    tf32_round_kernel<<<n4 / 256, 256>>>((const float4*)sdw, (uint4*)p_sdw, n4);

    // 1. router (+ g_scale, router_scores output)
    router_kernel<<<T_TOK, 256>>>(hs, rw, scores);

    // 2-3. expert path (fp32 GEMV, data-dependent skip)
    expert_gateup_kernel<<<dim3(I_DIM / 8, E_NUM), 256>>>(hs, egw, euw);
    expert_down_kernel<<<H_DIM, 256>>>(edw);

    // 4. gate = hs @ sgw^T           [T, I]
    gemm_tf32_mma<<<dim3(I_DIM / 128, T_TOK / 128), 256, GEMM_SMEM>>>(
        p_hs, p_sgw, p_act, H_DIM, I_DIM, nullptr, nullptr, 0);
    // 5. act = silu(gate) * (hs @ suw^T)   (fused epilogue, rounded to tf32)
    gemm_tf32_mma<<<dim3(I_DIM / 128, T_TOK / 128), 256, GEMM_SMEM>>>(
        p_hs, p_suw, p_act, H_DIM, I_DIM, nullptr, p_act, 1);
    // 6. out = act @ sdw^T + expert_sum    [T, H]
    gemm_tf32_mma<<<dim3(H_DIM / 128, T_TOK / 128), 256, GEMM_SMEM>>>(
        p_act, p_sdw, out, I_DIM, H_DIM, p_esum, nullptr, 0);
}